// round 11
// baseline (speedup 1.0000x reference)
#include <cuda_runtime.h>
#include <cstdint>
#include <math.h>

// Shapes (fixed): B=16, N=1024, C=768, H=12, hd=64
#define DIMK 768
#define HEADS 12

// ---------------- scratch (no cudaMalloc allowed) ----------------
__device__ __align__(16) float g_q[12582912];   // [B*H][1024][64], tf32-rounded, pre-scaled
__device__ __align__(16) float g_k[12582912];   // [B*H][1024][64], tf32-rounded
__device__ __align__(16) float g_v[12582912];   // [B*H][64][1024]  V^T, tf32-rounded
__device__ __align__(16) float g_ao[12582912];  // [B*N][768] attn out, tf32-rounded
__device__ __align__(16) float g_xr[12582912];  // X pre-rounded to tf32
__device__ __align__(16) float g_wq[1769472];   // qkv_w pre-rounded
__device__ __align__(16) float g_wp[589824];    // proj_w pre-rounded

// ---------------- PTX helpers ----------------
__device__ __forceinline__ uint32_t smem_u32(const void* p) {
    uint32_t a;
    asm("{ .reg .u64 t; cvta.to.shared.u64 t, %1; cvt.u32.u64 %0, t; }" : "=r"(a) : "l"(p));
    return a;
}
__device__ __forceinline__ void cp16(uint32_t dst, const void* src) {
    asm volatile("cp.async.cg.shared.global [%0], [%1], 16;" :: "r"(dst), "l"(src));
}
#define CP_COMMIT() asm volatile("cp.async.commit_group;" ::: "memory")
#define CP_WAIT1()  asm volatile("cp.async.wait_group 1;" ::: "memory")

__device__ __forceinline__ void ldsm4(uint32_t& r0, uint32_t& r1, uint32_t& r2, uint32_t& r3,
                                      uint32_t addr) {
    asm volatile("ldmatrix.sync.aligned.m8n8.x4.shared.b16 {%0,%1,%2,%3}, [%4];"
                 : "=r"(r0), "=r"(r1), "=r"(r2), "=r"(r3) : "r"(addr));
}
__device__ __forceinline__ uint32_t f2tf(float f) {
    uint32_t r;
    asm volatile("cvt.rna.tf32.f32 %0, %1;" : "=r"(r) : "f"(f));
    return r;
}
__device__ __forceinline__ float rtf(float f) { return __uint_as_float(f2tf(f)); }
__device__ __forceinline__ void mma_tf32(float c[4], const uint32_t a[4],
                                         uint32_t b0, uint32_t b1) {
    asm volatile("mma.sync.aligned.m16n8k8.row.col.f32.tf32.tf32.f32 "
                 "{%0,%1,%2,%3}, {%4,%5,%6,%7}, {%8,%9}, {%0,%1,%2,%3};"
                 : "+f"(c[0]), "+f"(c[1]), "+f"(c[2]), "+f"(c[3])
                 : "r"(a[0]), "r"(a[1]), "r"(a[2]), "r"(a[3]), "r"(b0), "r"(b1));
}

// ---------------- fused pre-round to tf32 ----------------
#define N4_X  3145728
#define N4_WQ 442368
#define N4_WP 147456
#define N4_ALL (N4_X + N4_WQ + N4_WP)

__global__ void preround_all(const float4* __restrict__ x, const float4* __restrict__ wq,
                             const float4* __restrict__ wp)
{
    int i = blockIdx.x * blockDim.x + threadIdx.x;
    const float4* s;
    float4* d;
    int k;
    if (i < N4_X)                { s = x;  d = (float4*)g_xr; k = i; }
    else if (i < N4_X + N4_WQ)   { s = wq; d = (float4*)g_wq; k = i - N4_X; }
    else if (i < N4_ALL)         { s = wp; d = (float4*)g_wp; k = i - N4_X - N4_WQ; }
    else return;
    float4 v = s[k];
    v.x = rtf(v.x); v.y = rtf(v.y); v.z = rtf(v.z); v.w = rtf(v.w);
    d[k] = v;
}

// ======================= GEMM (mma.sync tf32, operands pre-rounded) =======================
// C[m][n] = sum_k A[m][k] * W[n][k]. BM=128 BN=128 BK=32, 128 thr (4 warps 2x2),
// warp tile 64x64. Smem: 16B atoms, atom (row,k4) at row*128 + ((k4^row&7)<<4).
#define GSTG_BYTES 32768
#define GSM_TOTAL (3 * GSTG_BYTES)

__device__ __forceinline__ void g_load_stage(uint32_t sbase, const float* __restrict__ Ag,
                                             const float* __restrict__ Bg, int kt, int tid)
{
    const int kof = kt * 32;
#pragma unroll
    for (int i = 0; i < 8; i++) {
        int a = i * 128 + tid;
        int row = a >> 3, k4 = a & 7;
        cp16(sbase + row * 128 + (((k4 ^ row) & 7) << 4),
             Ag + (size_t)row * DIMK + kof + k4 * 4);
    }
#pragma unroll
    for (int i = 0; i < 8; i++) {
        int a = i * 128 + tid;
        int row = a >> 3, k4 = a & 7;
        cp16(sbase + 16384 + row * 128 + (((k4 ^ row) & 7) << 4),
             Bg + (size_t)row * DIMK + kof + k4 * 4);
    }
}

__device__ __forceinline__ void g_compute(uint32_t abase, uint32_t bbase,
                                          float acc[4][8][4], int lane, int wm, int wn)
{
    const int l15 = lane & 15;
    const int lhi = lane >> 4;
    const int brow_in = (lane & 7) + ((lane >> 4) << 3);
    const int bk_sel = (lane >> 3) & 1;
#pragma unroll
    for (int ks = 0; ks < 4; ks++) {
        uint32_t ar[4][4];
#pragma unroll
        for (int i = 0; i < 4; i++) {
            int row = wm * 64 + i * 16 + l15;
            int k4 = ks * 2 + lhi;
            ldsm4(ar[i][0], ar[i][1], ar[i][2], ar[i][3],
                  abase + row * 128 + (((k4 ^ row) & 7) << 4));
        }
        uint32_t br[8][2];
#pragma unroll
        for (int p = 0; p < 4; p++) {
            int row = wn * 64 + p * 16 + brow_in;
            int k4 = ks * 2 + bk_sel;
            uint32_t r0, r1, r2, r3;
            ldsm4(r0, r1, r2, r3, bbase + row * 128 + (((k4 ^ row) & 7) << 4));
            br[2 * p][0] = r0; br[2 * p][1] = r1;
            br[2 * p + 1][0] = r2; br[2 * p + 1][1] = r3;
        }
#pragma unroll
        for (int i = 0; i < 4; i++)
#pragma unroll
            for (int j = 0; j < 8; j++)
                mma_tf32(acc[i][j], ar[i], br[j][0], br[j][1]);
    }
}

// one 128x128 GEMM tile; caller must __syncthreads before calling when smem is live
__device__ __forceinline__ void gemm_tile(uint32_t sb, const float* __restrict__ Ag,
                                          const float* __restrict__ Bg,
                                          float acc[4][8][4], int tid, int lane, int wm, int wn)
{
#pragma unroll
    for (int i = 0; i < 4; i++)
#pragma unroll
        for (int j = 0; j < 8; j++)
#pragma unroll
            for (int q = 0; q < 4; q++) acc[i][j][q] = 0.f;
    g_load_stage(sb, Ag, Bg, 0, tid); CP_COMMIT();
    g_load_stage(sb + GSTG_BYTES, Ag, Bg, 1, tid); CP_COMMIT();
    for (int kt = 0; kt < 24; kt++) {
        CP_WAIT1();
        __syncthreads();
        if (kt + 2 < 24)
            g_load_stage(sb + ((kt + 2) % 3) * GSTG_BYTES, Ag, Bg, kt + 2, tid);
        CP_COMMIT();
        uint32_t st = sb + (kt % 3) * GSTG_BYTES;
        g_compute(st, st + 16384, acc, lane, wm, wn);
    }
}

__global__ __launch_bounds__(128, 2)
void gemm_qkv_mm(const float* __restrict__ bias)
{
    extern __shared__ char smem[];
    const uint32_t sb = smem_u32(smem);
    const int tid = threadIdx.x, lane = tid & 31, wid = tid >> 5;
    const int wm = wid & 1, wn = wid >> 1;
    const int m0 = blockIdx.y * 128;
    const int n0 = blockIdx.x * 128;

    float acc[4][8][4];
    gemm_tile(sb, g_xr + (size_t)m0 * DIMK, g_wq + (size_t)n0 * DIMK, acc, tid, lane, wm, wn);

    const int g = lane >> 2, t4 = lane & 3;
    const int cb = n0 + wn * 64;
    const int which = n0 / 768;            // uniform per CTA (boundaries at 768,1536)
    const int h = (cb % 768) / 64;
    if (which < 2) {
        const float scale = (which == 0) ? 0.125f : 1.0f;
        float* dst = (which == 0) ? g_q : g_k;
#pragma unroll
        for (int i = 0; i < 4; i++) {
#pragma unroll
            for (int j = 0; j < 8; j++) {
                const int col = j * 8 + t4 * 2;
                const float2 bv = *(const float2*)(bias + cb + col);
                int m = m0 + wm * 64 + i * 16 + g;
                int b = m >> 10, n = m & 1023;
                float2 v0 = make_float2(rtf((acc[i][j][0] + bv.x) * scale),
                                        rtf((acc[i][j][1] + bv.y) * scale));
                *(float2*)(dst + ((size_t)(b * HEADS + h) * 1024 + n) * 64 + col) = v0;
                m += 8; b = m >> 10; n = m & 1023;
                float2 v1 = make_float2(rtf((acc[i][j][2] + bv.x) * scale),
                                        rtf((acc[i][j][3] + bv.y) * scale));
                *(float2*)(dst + ((size_t)(b * HEADS + h) * 1024 + n) * 64 + col) = v1;
            }
        }
    } else {
        // V^T epilogue: stage transpose in smem (stage buffers free), coalesced stores.
        // st[col][row]: col = local n-col 0..127, row = local m 0..127, stride 132.
        float* st = (float*)smem;
        __syncthreads();   // mainloop smem reads fully done
#pragma unroll
        for (int i = 0; i < 4; i++) {
#pragma unroll
            for (int j = 0; j < 8; j++) {
                const int ccl = wn * 64 + j * 8 + t4 * 2;
                const float2 bv = *(const float2*)(bias + n0 + ccl);
                const int rr = wm * 64 + i * 16 + g;
                st[(ccl + 0) * 132 + rr] = rtf(acc[i][j][0] + bv.x);
                st[(ccl + 1) * 132 + rr] = rtf(acc[i][j][1] + bv.y);
                st[(ccl + 0) * 132 + rr + 8] = rtf(acc[i][j][2] + bv.x);
                st[(ccl + 1) * 132 + rr + 8] = rtf(acc[i][j][3] + bv.y);
            }
        }
        __syncthreads();
        const int b = m0 >> 10;
        const int nb = m0 & 1023;
#pragma unroll
        for (int it = 0; it < 32; it++) {
            const int idx = it * 128 + tid;     // 0..4095
            const int colg = idx >> 5;          // 0..127 local V col
            const int p4 = idx & 31;            // float4 within the 128-n row
            float4 v = *(float4*)&st[colg * 132 + p4 * 4];
            const int gcol = n0 - 1536 + colg;  // global V col 0..767
            const int hh = gcol >> 6, d = gcol & 63;
            *(float4*)(g_v + (size_t)(b * HEADS + hh) * 65536 + (size_t)d * 1024 + nb + p4 * 4) = v;
        }
    }
}

// persistent proj: 768 tiles (128 m-blocks x 6 n-blocks), grid-stride
__global__ __launch_bounds__(128, 2)
void gemm_proj_mm(const float* __restrict__ bias, float* __restrict__ out)
{
    extern __shared__ char smem[];
    const uint32_t sb = smem_u32(smem);
    const int tid = threadIdx.x, lane = tid & 31, wid = tid >> 5;
    const int wm = wid & 1, wn = wid >> 1;
    const int g = lane >> 2, t4 = lane & 3;

    for (int t = blockIdx.x; t < 768; t += gridDim.x) {
        const int m0 = (t / 6) * 128;
        const int n0 = (t % 6) * 128;
        __syncthreads();   // protect stage buffers across tiles
        float acc[4][8][4];
        gemm_tile(sb, g_ao + (size_t)m0 * DIMK, g_wp + (size_t)n0 * DIMK, acc, tid, lane, wm, wn);

#pragma unroll
        for (int i = 0; i < 4; i++) {
#pragma unroll
            for (int j = 0; j < 8; j++) {
                const int col = n0 + wn * 64 + j * 8 + t4 * 2;
                const float2 bv = *(const float2*)(bias + col);
                const int m = m0 + wm * 64 + i * 16 + g;
                *(float2*)(out + (size_t)m * DIMK + col) =
                    make_float2(acc[i][j][0] + bv.x, acc[i][j][1] + bv.y);
                *(float2*)(out + (size_t)(m + 8) * DIMK + col) =
                    make_float2(acc[i][j][2] + bv.x, acc[i][j][3] + bv.y);
            }
        }
    }
}

// ======================= Flash attention (mma.sync tf32, persistent) =======================
// 128 thr (4 warps), Br=128 (32 rows/warp: 2 m16 blocks), Bc=64, d=64.
// 1536 tiles = 192 bh x 8 q-blocks; t>>3 = bh (groups q-blocks for K/V L2 reuse).
#define AQ_OFF 0                 // 32768
#define AK_OFF 32768             // 2 x 16384
#define AV_OFF 65536             // 2 x 16384
#define ASM_TOTAL 98304

__device__ __forceinline__ uint32_t qk_addr(uint32_t base, int row, int k4) {
    return base + row * 256 + ((((k4 & 8) | ((k4 ^ row) & 7))) << 4);
}

__global__ __launch_bounds__(128, 2)
void attn_mm()
{
    extern __shared__ char smem[];
    const uint32_t sb = smem_u32(smem);

    const int tid = threadIdx.x, lane = tid & 31, w = tid >> 5;
    const int g = lane >> 2, t4 = lane & 3;

    const int a_l15 = lane & 15, a_lhi = lane >> 4;
    const int b_row_in = (lane & 7) + ((lane >> 4) << 3);
    const int b_k_sel = (lane >> 3) & 1;
    const int lsA = (lane & ~3) + (t4 >> 1);       // P-shuffle source lanes
    const int lsB = lsA + 2;
    const bool odd = (t4 & 1);

    for (int t = blockIdx.x; t < 1536; t += gridDim.x) {
        const int bh = t >> 3;
        const int r0 = (t & 7) * 128;
        const float* qp = g_q + ((size_t)bh * 1024 + r0) * 64;
        const float* kbase = g_k + (size_t)bh * 65536;
        const float* vtb = g_v + (size_t)bh * 65536;   // [64][1024]

        __syncthreads();   // previous tile's smem reads complete before prologue writes

        // prologue: Q (128x16 atoms) + chunk0 K/V^T (64x16 atoms each)
#pragma unroll
        for (int i = 0; i < 16; i++) {
            int a = i * 128 + tid;
            int row = a >> 4, k4 = a & 15;
            cp16(qk_addr(sb + AQ_OFF, row, k4), qp + (size_t)row * 64 + k4 * 4);
        }
#pragma unroll
        for (int i = 0; i < 8; i++) {
            int a = i * 128 + tid;
            int row = a >> 4, k4 = a & 15;
            cp16(qk_addr(sb + AK_OFF, row, k4), kbase + (size_t)row * 64 + k4 * 4);
            cp16(qk_addr(sb + AV_OFF, row, k4), vtb + (size_t)row * 1024 + k4 * 4);
        }
        CP_COMMIT();

        float o[2][8][4];
        float m_run[2][2], l_run[2][2];
#pragma unroll
        for (int i = 0; i < 2; i++) {
            m_run[i][0] = -1e30f; m_run[i][1] = -1e30f;
            l_run[i][0] = 0.f;    l_run[i][1] = 0.f;
#pragma unroll
            for (int j = 0; j < 8; j++)
#pragma unroll
                for (int q = 0; q < 4; q++) o[i][j][q] = 0.f;
        }

        for (int c = 0; c < 16; c++) {
            __syncthreads();
            if (c + 1 < 16) {
                const uint32_t kb2 = sb + AK_OFF + ((c + 1) & 1) * 16384;
                const uint32_t vb2 = sb + AV_OFF + ((c + 1) & 1) * 16384;
                const float* ksrc = kbase + (size_t)(c + 1) * 4096;
                const float* vsrc = vtb + (size_t)(c + 1) * 64;
#pragma unroll
                for (int i = 0; i < 8; i++) {
                    int a = i * 128 + tid;
                    int row = a >> 4, k4 = a & 15;
                    cp16(qk_addr(kb2, row, k4), ksrc + (size_t)row * 64 + k4 * 4);
                    cp16(qk_addr(vb2, row, k4), vsrc + (size_t)row * 1024 + k4 * 4);
                }
            }
            CP_COMMIT();
            CP_WAIT1();
            __syncthreads();

            const uint32_t kb = sb + AK_OFF + (c & 1) * 16384;
            const uint32_t vb = sb + AV_OFF + (c & 1) * 16384;

            // ---- S = Q @ K^T (Q pre-scaled) ----
            float s[2][8][4];
#pragma unroll
            for (int i = 0; i < 2; i++)
#pragma unroll
                for (int j = 0; j < 8; j++)
#pragma unroll
                    for (int q = 0; q < 4; q++) s[i][j][q] = 0.f;
#pragma unroll
            for (int ks = 0; ks < 8; ks++) {
                uint32_t ar[2][4];
#pragma unroll
                for (int i = 0; i < 2; i++) {
                    int row = w * 32 + i * 16 + a_l15;
                    int k4 = ks * 2 + a_lhi;
                    ldsm4(ar[i][0], ar[i][1], ar[i][2], ar[i][3], qk_addr(sb + AQ_OFF, row, k4));
                }
#pragma unroll
                for (int p = 0; p < 4; p++) {
                    int row = p * 16 + b_row_in;
                    int k4 = ks * 2 + b_k_sel;
                    uint32_t r0b, r1b, r2b, r3b;
                    ldsm4(r0b, r1b, r2b, r3b, qk_addr(kb, row, k4));
#pragma unroll
                    for (int i = 0; i < 2; i++) {
                        mma_tf32(s[i][2 * p], ar[i], r0b, r1b);
                        mma_tf32(s[i][2 * p + 1], ar[i], r2b, r3b);
                    }
                }
            }

            // ---- online softmax per m16 block ----
#pragma unroll
            for (int i = 0; i < 2; i++) {
                float mx0 = -1e30f, mx1 = -1e30f;
#pragma unroll
                for (int j = 0; j < 8; j++) {
                    mx0 = fmaxf(mx0, fmaxf(s[i][j][0], s[i][j][1]));
                    mx1 = fmaxf(mx1, fmaxf(s[i][j][2], s[i][j][3]));
                }
                mx0 = fmaxf(mx0, __shfl_xor_sync(0xffffffffu, mx0, 1));
                mx0 = fmaxf(mx0, __shfl_xor_sync(0xffffffffu, mx0, 2));
                mx1 = fmaxf(mx1, __shfl_xor_sync(0xffffffffu, mx1, 1));
                mx1 = fmaxf(mx1, __shfl_xor_sync(0xffffffffu, mx1, 2));
                const float mn0 = fmaxf(m_run[i][0], mx0), mn1 = fmaxf(m_run[i][1], mx1);
                float sum0 = 0.f, sum1 = 0.f;
#pragma unroll
                for (int j = 0; j < 8; j++) {
                    s[i][j][0] = rtf(__expf(s[i][j][0] - mn0));
                    s[i][j][1] = rtf(__expf(s[i][j][1] - mn0));
                    s[i][j][2] = rtf(__expf(s[i][j][2] - mn1));
                    s[i][j][3] = rtf(__expf(s[i][j][3] - mn1));
                    sum0 += s[i][j][0] + s[i][j][1];
                    sum1 += s[i][j][2] + s[i][j][3];
                }
                sum0 += __shfl_xor_sync(0xffffffffu, sum0, 1);
                sum0 += __shfl_xor_sync(0xffffffffu, sum0, 2);
                sum1 += __shfl_xor_sync(0xffffffffu, sum1, 1);
                sum1 += __shfl_xor_sync(0xffffffffu, sum1, 2);
                const float al0 = __expf(m_run[i][0] - mn0), al1 = __expf(m_run[i][1] - mn1);
                l_run[i][0] = l_run[i][0] * al0 + sum0;
                l_run[i][1] = l_run[i][1] * al1 + sum1;
                m_run[i][0] = mn0; m_run[i][1] = mn1;
#pragma unroll
                for (int j = 0; j < 8; j++) {
                    o[i][j][0] *= al0; o[i][j][1] *= al0;
                    o[i][j][2] *= al1; o[i][j][3] *= al1;
                }
            }

            // ---- O += P @ V : P accum->A-frag via shuffles, V^T via ldmatrix ----
#pragma unroll
            for (int kk = 0; kk < 8; kk++) {
                uint32_t vr[8][2];
#pragma unroll
                for (int p = 0; p < 4; p++) {
                    int row = p * 16 + b_row_in;        // d-dim
                    int k4 = kk * 2 + b_k_sel;          // key-dim atoms
                    uint32_t r0b, r1b, r2b, r3b;
                    ldsm4(r0b, r1b, r2b, r3b, qk_addr(vb, row, k4));
                    vr[2 * p][0] = r0b; vr[2 * p][1] = r1b;
                    vr[2 * p + 1][0] = r2b; vr[2 * p + 1][1] = r3b;
                }
#pragma unroll
                for (int i = 0; i < 2; i++) {
                    const float u0 = __shfl_sync(0xffffffffu, s[i][kk][0], lsA);
                    const float u1 = __shfl_sync(0xffffffffu, s[i][kk][1], lsA);
                    const float u2 = __shfl_sync(0xffffffffu, s[i][kk][2], lsA);
                    const float u3 = __shfl_sync(0xffffffffu, s[i][kk][3], lsA);
                    const float w0 = __shfl_sync(0xffffffffu, s[i][kk][0], lsB);
                    const float w1 = __shfl_sync(0xffffffffu, s[i][kk][1], lsB);
                    const float w2 = __shfl_sync(0xffffffffu, s[i][kk][2], lsB);
                    const float w3 = __shfl_sync(0xffffffffu, s[i][kk][3], lsB);
                    uint32_t pa[4];
                    pa[0] = __float_as_uint(odd ? u1 : u0);
                    pa[1] = __float_as_uint(odd ? u3 : u2);
                    pa[2] = __float_as_uint(odd ? w1 : w0);
                    pa[3] = __float_as_uint(odd ? w3 : w2);
#pragma unroll
                    for (int j = 0; j < 8; j++)
                        mma_tf32(o[i][j], pa, vr[j][0], vr[j][1]);
                }
            }
        }

        // epilogue -> g_ao [B*N][768], tf32-rounded for proj consumption
        const int b = bh / HEADS, h = bh % HEADS;
#pragma unroll
        for (int i = 0; i < 2; i++) {
            const float i0 = 1.0f / l_run[i][0], i1 = 1.0f / l_run[i][1];
            const int na = r0 + w * 32 + i * 16 + g;
#pragma unroll
            for (int j = 0; j < 8; j++) {
                const int col = h * 64 + j * 8 + t4 * 2;
                *(float2*)(g_ao + ((size_t)(b * 1024 + na)) * DIMK + col) =
                    make_float2(rtf(o[i][j][0] * i0), rtf(o[i][j][1] * i0));
                *(float2*)(g_ao + ((size_t)(b * 1024 + na + 8)) * DIMK + col) =
                    make_float2(rtf(o[i][j][2] * i1), rtf(o[i][j][3] * i1));
            }
        }
    }
}

// ---------------- launch ----------------
extern "C" void kernel_launch(void* const* d_in, const int* in_sizes, int n_in,
                              void* d_out, int out_size)
{
    const float* x      = (const float*)d_in[0];
    const float* qkv_w  = (const float*)d_in[1];
    const float* qkv_b  = (const float*)d_in[2];
    // d_in[3] = qkv_B (unused feedback-alignment buffer)
    const float* proj_w = (const float*)d_in[4];
    const float* proj_b = (const float*)d_in[5];
    // d_in[6] = proj_B (unused)
    float* out = (float*)d_out;

    cudaFuncSetAttribute(gemm_qkv_mm, cudaFuncAttributeMaxDynamicSharedMemorySize, GSM_TOTAL);
    cudaFuncSetAttribute(gemm_proj_mm, cudaFuncAttributeMaxDynamicSharedMemorySize, GSM_TOTAL);
    cudaFuncSetAttribute(attn_mm, cudaFuncAttributeMaxDynamicSharedMemorySize, ASM_TOTAL);

    preround_all<<<(N4_ALL + 255) / 256, 256>>>((const float4*)x, (const float4*)qkv_w,
                                                (const float4*)proj_w);

    gemm_qkv_mm<<<dim3(18, 128), 128, GSM_TOTAL>>>(qkv_b);
    attn_mm<<<296, 128, ASM_TOTAL>>>();
    gemm_proj_mm<<<296, 128, GSM_TOTAL>>>(proj_b, out);
}